// round 5
// baseline (speedup 1.0000x reference)
#include <cuda_runtime.h>

#define NN 2000
#define KX 16
#define CH 16
#define NODE_TILE (KX * KX * CH)  // 4096 floats per node

// ---------------- device scratch (static globals: allocation-free) ----------
__device__ int g_nbrs[NN * KX];
__device__ __align__(16) float g_F1[(size_t)NN * NODE_TILE];  // 32 MB
__device__ double g_gsum[48];

// ---------------- shared layout for the step kernel -------------------------
struct SmemStep {
    float tile[KX][KX][CH];   // F[j] tile (or diag(X) for layer 1)
    float s0[KX][KX][CH];     // sum over m              [a][b][c]
    float s1[KX][KX][CH];     // sum over a              [m][b][c]
    float s2[KX][KX][CH];     // sum over b              [m][a][c]
    float d0[KX][KX][CH];     // T[m, m, b, c]           [m][b][c]
    float d1[KX][KX][CH];     // T[m, a, m, c]           [m][a][c]
    float d2[KX][KX][CH];     // T[m, y, y, c]           [m][y][c]
    float v0[KX][CH];         // sum over (a,b)          [m][c]
    float v1[KX][CH];         // sum over (m,b)          [a][c]
    float v2[KX][CH];         // sum over (m,a)          [b][c]
    float W[16][288];         // weight matrix [h][18*16]
    float rowt[KX][16];       // rowterm[alpha][h]
    float colt[KX][16];       // colterm[beta][h]
    float bb[16];
    int nbrs_i[KX];
    int nbrs_j[KX];
    int pi[KX];
    float red[8][16];         // per-warp partials for g reduction
};

// ---------------- kernel 1: neighbor extraction + zero g --------------------
// One warp per row. adj row has exactly K ones; collect their column indices
// in ascending order (matches sort(top_k)).
__global__ void nbrs_kernel(const float* __restrict__ adj) {
    if (blockIdx.x == 0 && threadIdx.x < 48) g_gsum[threadIdx.x] = 0.0;
    int w = blockIdx.x * (blockDim.x >> 5) + (threadIdx.x >> 5);
    int lane = threadIdx.x & 31;
    if (w >= NN) return;
    const float* row = adj + (size_t)w * NN;
    int cnt = 0;
    for (int base = 0; base < NN; base += 32) {
        int col = base + lane;
        float v = (col < NN) ? row[col] : 0.f;
        unsigned mask = __ballot_sync(0xffffffffu, v > 0.5f);
        if (v > 0.5f) {
            int pos = cnt + __popc(mask & ((1u << lane) - 1u));
            if (pos < KX) g_nbrs[w * KX + pos] = col;
        }
        cnt += __popc(mask);
    }
}

// ---------------- kernel 2: F0 channel sums = sum_{i,a} X[nbrs[i,a], c] -----
__global__ void f0sum_kernel(const float* __restrict__ X) {
    int idx = blockIdx.x * 256 + threadIdx.x;  // flat (i,a) pair, 32000 total
    float loc[16];
#pragma unroll
    for (int c = 0; c < 16; ++c) loc[c] = 0.f;
    if (idx < NN * KX) {
        int node = g_nbrs[idx];
#pragma unroll
        for (int c = 0; c < 16; ++c) loc[c] = X[node * 16 + c];
    }
#pragma unroll
    for (int c = 0; c < 16; ++c) {
        float v = loc[c];
#pragma unroll
        for (int o = 16; o; o >>= 1) v += __shfl_xor_sync(0xffffffffu, v, o);
        loc[c] = v;
    }
    __shared__ float sh[8][16];
    int wid = threadIdx.x >> 5, lane = threadIdx.x & 31;
    if (lane == 0) {
#pragma unroll
        for (int c = 0; c < 16; ++c) sh[wid][c] = loc[c];
    }
    __syncthreads();
    if (threadIdx.x < 16) {
        float s = 0.f;
#pragma unroll
        for (int w = 0; w < 8; ++w) s += sh[w][threadIdx.x];
        atomicAdd(&g_gsum[threadIdx.x], (double)s);
    }
}

// ---------------- kernel 3/4: one CCN step (MODE 1: F=F0 from X, writes F1;
//                              MODE 2: F=F1, no output tensor) ---------------
template <int MODE>
__global__ __launch_bounds__(256, 1) void step_kernel(
    const float* __restrict__ X, const float* __restrict__ Wg,
    const float* __restrict__ bg) {
    extern __shared__ char smraw[];
    SmemStep* sm = reinterpret_cast<SmemStep*>(smraw);
    const int i = blockIdx.x;
    const int tid = threadIdx.x;

    if (tid < KX) sm->nbrs_i[tid] = g_nbrs[i * KX + tid];
    for (int idx = tid; idx < NODE_TILE; idx += 256) (&sm->s0[0][0][0])[idx] = 0.f;
    if (tid < KX * CH) {
        (&sm->v1[0][0])[tid] = 0.f;
        (&sm->v2[0][0])[tid] = 0.f;
    }
    for (int idx = tid; idx < 16 * 288; idx += 256) (&sm->W[0][0])[idx] = Wg[idx];
    if (tid < 16) sm->bb[tid] = bg[tid];
    __syncthreads();

    // ---------------- Phase A: accumulate the 9 contraction arrays ----------
    for (int m = 0; m < KX; ++m) {
        int j = sm->nbrs_i[m];
        if (tid < KX) sm->nbrs_j[tid] = g_nbrs[j * KX + tid];
        __syncthreads();
        if (tid < KX) {
            int tgt = sm->nbrs_i[tid];
            int p = -1;
#pragma unroll
            for (int q = 0; q < KX; ++q)
                if (sm->nbrs_j[q] == tgt) p = q;
            sm->pi[tid] = p;
        }
        if (MODE == 1) {
            // F0[j] is diagonal: tile[p][q][c] = (p==q) * X[nbrs_j[p], c]
            for (int idx = tid; idx < NODE_TILE; idx += 256) {
                int p = idx >> 8, q = (idx >> 4) & 15, c = idx & 15;
                sm->tile[p][q][c] = (p == q) ? X[sm->nbrs_j[p] * CH + c] : 0.f;
            }
        } else {
            const float4* src =
                reinterpret_cast<const float4*>(g_F1 + (size_t)j * NODE_TILE);
            float4* dst = reinterpret_cast<float4*>(&sm->tile[0][0][0]);
            for (int idx = tid; idx < NODE_TILE / 4; idx += 256) dst[idx] = src[idx];
        }
        __syncthreads();

        // P12: thread = (a, c); loop over b.  T_m[a,b,c] = tile[pi[a]][pi[b]][c]
        {
            int a = tid >> 4, c = tid & 15;
            int pa = sm->pi[a];
            float sum = 0.f;
#pragma unroll
            for (int b = 0; b < KX; ++b) {
                int pb = sm->pi[b];
                float v = (pa >= 0 && pb >= 0) ? sm->tile[pa][pb][c] : 0.f;
                sum += v;
                sm->s0[a][b][c] += v;
                if (a == m) sm->d0[m][b][c] = v;  // T[m, b]
                if (b == m) sm->d1[m][a][c] = v;  // T[a, m]
                if (b == a) sm->d2[m][a][c] = v;  // T[a, a]
            }
            sm->s2[m][a][c] = sum;   // sum over b
            sm->v1[a][c] += sum;     // sum over (m,b)
        }
        // P3: thread = (b, c); loop over a
        {
            int b = tid >> 4, c = tid & 15;
            int pb = sm->pi[b];
            float sum = 0.f;
            if (pb >= 0) {
#pragma unroll
                for (int a = 0; a < KX; ++a) {
                    int pa = sm->pi[a];
                    if (pa >= 0) sum += sm->tile[pa][pb][c];
                }
            }
            sm->s1[m][b][c] = sum;   // sum over a
            sm->v2[b][c] += sum;     // sum over (m,a)
        }
        __syncthreads();
        if (tid < 16) {  // v0[m][c] = sum_a s2[m][a][c]
            float s = 0.f;
#pragma unroll
            for (int a = 0; a < KX; ++a) s += sm->s2[m][a][tid];
            sm->v0[m][tid] = s;
        }
        __syncthreads();
    }

    // ---------------- Phase B: 18-block GEMM + ReLU + sums -------------------
    // rowterm/colterm from the broadcast blocks 12..17
    {
        int al = tid >> 4, h = tid & 15;
        float r = 0.f, ct = 0.f;
#pragma unroll
        for (int c = 0; c < CH; ++c) {
            float a0 = sm->v0[al][c], a1 = sm->v1[al][c], a2 = sm->v2[al][c];
            r  += a0 * sm->W[h][12 * CH + c] + a1 * sm->W[h][14 * CH + c] +
                  a2 * sm->W[h][16 * CH + c];
            ct += a0 * sm->W[h][13 * CH + c] + a1 * sm->W[h][15 * CH + c] +
                  a2 * sm->W[h][17 * CH + c];
        }
        sm->rowt[al][h] = r;
        sm->colt[al][h] = ct;
    }
    __syncthreads();

    int al = tid >> 4, be = tid & 15;
    float acc[16];
#pragma unroll
    for (int h = 0; h < 16; ++h)
        acc[h] = sm->bb[h] + sm->rowt[al][h] + sm->colt[be][h];

#define DO_BLOCK(ARR, BE, BO)                                              \
    {                                                                      \
        const float* pab = &sm->ARR[al][be][0];                            \
        const float* pba = &sm->ARR[be][al][0];                            \
        for (int c = 0; c < CH; ++c) {                                     \
            float va = pab[c], vb = pba[c];                                \
            _Pragma("unroll")                                              \
            for (int h = 0; h < 16; ++h)                                   \
                acc[h] += va * sm->W[h][(BE) * CH + c] +                   \
                          vb * sm->W[h][(BO) * CH + c];                    \
        }                                                                  \
    }
    DO_BLOCK(s0, 0, 1)
    DO_BLOCK(s1, 2, 3)
    DO_BLOCK(s2, 4, 5)
    DO_BLOCK(d0, 6, 7)
    DO_BLOCK(d1, 8, 9)
    DO_BLOCK(d2, 10, 11)
#undef DO_BLOCK

#pragma unroll
    for (int h = 0; h < 16; ++h) acc[h] = fmaxf(acc[h], 0.f);

    if (MODE == 1) {
        float4* out =
            reinterpret_cast<float4*>(g_F1 + (size_t)i * NODE_TILE + tid * 16);
        out[0] = make_float4(acc[0], acc[1], acc[2], acc[3]);
        out[1] = make_float4(acc[4], acc[5], acc[6], acc[7]);
        out[2] = make_float4(acc[8], acc[9], acc[10], acc[11]);
        out[3] = make_float4(acc[12], acc[13], acc[14], acc[15]);
    }

    // per-h block reduction -> g accumulators
#pragma unroll
    for (int h = 0; h < 16; ++h) {
        float v = acc[h];
#pragma unroll
        for (int o = 16; o; o >>= 1) v += __shfl_xor_sync(0xffffffffu, v, o);
        acc[h] = v;
    }
    int wid = tid >> 5, lane = tid & 31;
    if (lane == 0) {
#pragma unroll
        for (int h = 0; h < 16; ++h) sm->red[wid][h] = acc[h];
    }
    __syncthreads();
    if (tid < 16) {
        float s = 0.f;
#pragma unroll
        for (int w = 0; w < 8; ++w) s += sm->red[w][tid];
        atomicAdd(&g_gsum[(MODE == 1 ? 16 : 32) + tid], (double)s);
    }
}

// ---------------- kernel 5: final dot with fc --------------------------------
__global__ void final_kernel(const float* __restrict__ fc_w,
                             const float* __restrict__ fc_b,
                             float* __restrict__ out) {
    if (threadIdx.x == 0) {
        double s = (double)fc_b[0];
#pragma unroll
        for (int c = 0; c < 48; ++c) s += g_gsum[c] * (double)fc_w[c];
        out[0] = (float)s;
    }
}

// ---------------- host entry --------------------------------------------------
extern "C" void kernel_launch(void* const* d_in, const int* in_sizes, int n_in,
                              void* d_out, int out_size) {
    const float* X   = (const float*)d_in[0];
    const float* adj = (const float*)d_in[1];
    const float* W1  = (const float*)d_in[2];
    const float* b1  = (const float*)d_in[3];
    const float* W2  = (const float*)d_in[4];
    const float* b2  = (const float*)d_in[5];
    const float* fcw = (const float*)d_in[6];
    const float* fcb = (const float*)d_in[7];
    float* out = (float*)d_out;

    const int SMEM = (int)sizeof(SmemStep);
    cudaFuncSetAttribute(step_kernel<1>,
                         cudaFuncAttributeMaxDynamicSharedMemorySize, SMEM);
    cudaFuncSetAttribute(step_kernel<2>,
                         cudaFuncAttributeMaxDynamicSharedMemorySize, SMEM);

    nbrs_kernel<<<250, 256>>>(adj);
    f0sum_kernel<<<125, 256>>>(X);
    step_kernel<1><<<NN, 256, SMEM>>>(X, W1, b1);
    step_kernel<2><<<NN, 256, SMEM>>>(X, W2, b2);
    final_kernel<<<1, 32>>>(fcw, fcb, out);
}

// round 7
// speedup vs baseline: 2.9357x; 2.9357x over previous
#include <cuda_runtime.h>

#define NN 2000
#define KX 16
#define CH 16
#define NODE_TILE 4096
#define SPAD 20

// ---------------- device scratch (static globals: allocation-free) ----------
__device__ int g_nbrs[NN * KX];
__device__ __align__(16) float g_F1[(size_t)NN * NODE_TILE];  // 32 MB
__device__ double g_gsum[48];

// ---------------- shared layout for the step kernel -------------------------
// sp arrays use a swizzled padded layout: logical A[x][y][c] stored at
// sp[arr][x][y ^ x][c] with row pad SPAD=20 floats. Both A[al][be] and
// A[be][al] then land on physical column (al^be) -> identical, well-spread
// bank pattern for the transposed read in phase B.
struct Sm {
    float tile[4][NODE_TILE];     // phase A: 4 F[j] tiles; phase B: 4 partial acc buffers [csec][pos*16+h]
    float sp[6][KX][KX][SPAD];    // 0:s0 1:s1 2:s2 3:d0 4:d1 5:d2 (swizzled)
    float W[16][288];
    float v0[KX][CH];
    float v1p[4][KX][CH];
    float v2p[4][KX][CH];
    float rowt[KX][16];
    float colt[KX][16];
    float bb[16];
    float red[32][16];
    int nbrs_i[KX];
    int nbrs_j[4][KX];
    int pi[4][KX];
};

__device__ __forceinline__ unsigned long long ld2(const float* p) {
    return *reinterpret_cast<const unsigned long long*>(p);
}
#define FMA2(acc, x, y) \
    asm("fma.rn.f32x2 %0, %1, %2, %3;" : "=l"(acc) : "l"(x), "l"(y), "l"(acc))

// ---------------- kernel 1: neighbor extraction + zero g --------------------
__global__ void nbrs_kernel(const float* __restrict__ adj) {
    if (blockIdx.x == 0 && threadIdx.x < 48) g_gsum[threadIdx.x] = 0.0;
    int w = blockIdx.x * (blockDim.x >> 5) + (threadIdx.x >> 5);
    int lane = threadIdx.x & 31;
    if (w >= NN) return;
    const float* row = adj + (size_t)w * NN;
    int cnt = 0;
    for (int base = 0; base < NN; base += 32) {
        int col = base + lane;
        float v = (col < NN) ? row[col] : 0.f;
        unsigned mask = __ballot_sync(0xffffffffu, v > 0.5f);
        if (v > 0.5f) {
            int pos = cnt + __popc(mask & ((1u << lane) - 1u));
            if (pos < KX) g_nbrs[w * KX + pos] = col;
        }
        cnt += __popc(mask);
    }
}

// ---------------- kernel 2: F0 channel sums ---------------------------------
__global__ void f0sum_kernel(const float* __restrict__ X) {
    int idx = blockIdx.x * 256 + threadIdx.x;
    float loc[16];
#pragma unroll
    for (int c = 0; c < 16; ++c) loc[c] = 0.f;
    if (idx < NN * KX) {
        int node = g_nbrs[idx];
#pragma unroll
        for (int c = 0; c < 16; ++c) loc[c] = X[node * 16 + c];
    }
#pragma unroll
    for (int c = 0; c < 16; ++c) {
        float v = loc[c];
#pragma unroll
        for (int o = 16; o; o >>= 1) v += __shfl_xor_sync(0xffffffffu, v, o);
        loc[c] = v;
    }
    __shared__ float sh[8][16];
    int wid = threadIdx.x >> 5, lane = threadIdx.x & 31;
    if (lane == 0) {
#pragma unroll
        for (int c = 0; c < 16; ++c) sh[wid][c] = loc[c];
    }
    __syncthreads();
    if (threadIdx.x < 16) {
        float s = 0.f;
#pragma unroll
        for (int w = 0; w < 8; ++w) s += sh[w][threadIdx.x];
        atomicAdd(&g_gsum[threadIdx.x], (double)s);
    }
}

// ---------------- kernel 3/4: one CCN step ----------------------------------
// 1024 threads = 4 groups x 256. Group g handles m = iter*4+g.
template <int MODE>
__global__ __launch_bounds__(1024, 1) void step_kernel(
    const float* __restrict__ X, const float* __restrict__ Wg,
    const float* __restrict__ bg) {
    extern __shared__ char smraw[];
    Sm* sm = reinterpret_cast<Sm*>(smraw);
    const int i = blockIdx.x;
    const int tid = threadIdx.x;
    const int g = tid >> 8, t = tid & 255;
    const int xa = t >> 4, c = t & 15;

    if (tid < 16) sm->nbrs_i[tid] = g_nbrs[i * KX + tid];
    for (int idx = tid; idx < 16 * 288; idx += 1024) (&sm->W[0][0])[idx] = Wg[idx];
    if (tid >= 32 && tid < 48) sm->bb[tid - 32] = bg[tid - 32];
    __syncthreads();

    // ---------------- Phase A ------------------------------------------------
    float s0r[16];
#pragma unroll
    for (int b = 0; b < 16; ++b) s0r[b] = 0.f;
    float v1acc = 0.f, v2acc = 0.f;

    for (int iter = 0; iter < 4; ++iter) {
        const int m = iter * 4 + g;
        const int j = sm->nbrs_i[m];
        if (t < 16) {
            sm->nbrs_j[g][t] = g_nbrs[j * KX + t];
            __syncwarp(0x0000FFFFu);
            int tgt = sm->nbrs_i[t];
            int p = -1;
#pragma unroll
            for (int q = 0; q < 16; ++q)
                if (sm->nbrs_j[g][q] == tgt) p = q;
            sm->pi[g][t] = p;
        }
        if (MODE == 2) {
            const float4* src = (const float4*)(g_F1 + (size_t)j * NODE_TILE);
            float4* dst = (float4*)&sm->tile[g][0];
#pragma unroll
            for (int r = 0; r < 4; ++r) dst[t + 256 * r] = src[t + 256 * r];
        }
        __syncthreads();

        const int pa = sm->pi[g][xa];
        if (MODE == 1) {
            // F0[j] is diagonal: T_m[a,b,c] = (a==b) * X[nbrs_j[pi[a]], c]
            float xv = (pa >= 0) ? X[sm->nbrs_j[g][pa] * CH + c] : 0.f;
            s0r[xa] += xv;
            v1acc += xv;
            v2acc += xv;
            float dv = (xa == m) ? xv : 0.f;
            sm->sp[1][m][xa ^ m][c] = xv;   // s1[m][b]
            sm->sp[2][m][xa ^ m][c] = xv;   // s2[m][a]
            sm->sp[3][m][xa ^ m][c] = dv;   // d0[m][b]
            sm->sp[4][m][xa ^ m][c] = dv;   // d1[m][a]
            sm->sp[5][m][xa ^ m][c] = xv;   // d2[m][y]
        } else {
            const float* tg = &sm->tile[g][0];
            float rowSum = 0.f;
#pragma unroll
            for (int b = 0; b < 16; ++b) {
                int pb = sm->pi[g][b];
                float v = 0.f;
                if (pa >= 0 && pb >= 0) v = tg[pa * 256 + pb * 16 + c];
                s0r[b] += v;
                rowSum += v;
                if (b == m) sm->sp[4][m][xa ^ m][c] = v;   // d1[m][a] = T[a][m]
                if (b == xa) sm->sp[5][m][xa ^ m][c] = v;  // d2[m][y] = T[y][y]
                if (xa == m) sm->sp[3][m][b ^ m][c] = v;   // d0[m][b] = T[m][b]
            }
            sm->sp[2][m][xa ^ m][c] = rowSum;  // s2[m][a] = sum_b
            v1acc += rowSum;
            float colSum = 0.f;
            if (pa >= 0) {
#pragma unroll
                for (int a2 = 0; a2 < 16; ++a2) {
                    int p2 = sm->pi[g][a2];
                    if (p2 >= 0) colSum += tg[p2 * 256 + pa * 16 + c];
                }
            }
            sm->sp[1][m][xa ^ m][c] = colSum;  // s1[m][b] = sum_a
            v2acc += colSum;
        }
        __syncthreads();
        if (t < 16) {  // v0[m][c] = sum_a s2[m][a][c]
            float s = 0.f;
#pragma unroll
            for (int a2 = 0; a2 < 16; ++a2) s += sm->sp[2][m][a2 ^ m][t];
            sm->v0[m][t] = s;
        }
    }

    // s0 partials (registers -> tile buffers), v1/v2 partials
#pragma unroll
    for (int b = 0; b < 16; ++b) sm->tile[g][xa * 256 + b * 16 + c] = s0r[b];
    sm->v1p[g][xa][c] = v1acc;
    sm->v2p[g][xa][c] = v2acc;
    __syncthreads();
    // combine s0 into swizzled sp[0]
    for (int idx = tid; idx < NODE_TILE; idx += 1024) {
        int a2 = idx >> 8, b2 = (idx >> 4) & 15, c2 = idx & 15;
        float s = sm->tile[0][idx] + sm->tile[1][idx] + sm->tile[2][idx] +
                  sm->tile[3][idx];
        sm->sp[0][a2][b2 ^ a2][c2] = s;
    }
    __syncthreads();

    // ---------------- Phase B ------------------------------------------------
    // row/col broadcast terms (blocks 12..17)
    if (tid < 512) {
        const int half = tid >> 8;  // 0 -> rowt (even blocks), 1 -> colt (odd)
        const int al = (tid >> 4) & 15, h = tid & 15;
        const int off = half * 16;
        float acc = 0.f;
#pragma unroll
        for (int cc = 0; cc < 16; ++cc) {
            float a0 = sm->v0[al][cc];
            float a1 = sm->v1p[0][al][cc] + sm->v1p[1][al][cc] +
                       sm->v1p[2][al][cc] + sm->v1p[3][al][cc];
            float a2v = sm->v2p[0][al][cc] + sm->v2p[1][al][cc] +
                        sm->v2p[2][al][cc] + sm->v2p[3][al][cc];
            acc += a0 * sm->W[h][192 + off + cc] + a1 * sm->W[h][224 + off + cc] +
                   a2v * sm->W[h][256 + off + cc];
        }
        if (half == 0) sm->rowt[al][h] = acc;
        else           sm->colt[al][h] = acc;
    }

    // warp-GEMM: warp w -> 32 positions (pb block) x channel section csec.
    const int w = tid >> 5, lane = tid & 31;
    const int posb = (w & 7) * 32 + lane;
    const int alp = posb >> 4, bep = posb & 15;
    const int csec = w >> 3;
    const int colsw = alp ^ bep;  // swizzled physical column for BOTH va & vb
    unsigned long long acc2[16];
#pragma unroll
    for (int h = 0; h < 16; ++h) acc2[h] = 0ull;

#pragma unroll 2
    for (int u = 0; u < 12; ++u) {
        int kp = csec * 12 + u;          // 48 channel-pairs total
        int arr = kp >> 3;
        int cc = (kp & 7) * 2;
        const float* base = &sm->sp[arr][0][0][0];
        unsigned long long va2 = ld2(base + (alp * 16 + colsw) * SPAD + cc);
        unsigned long long vb2 = ld2(base + (bep * 16 + colsw) * SPAD + cc);
        const float* wp = &sm->W[0][arr * 32 + cc];
#pragma unroll
        for (int h = 0; h < 16; ++h) {
            unsigned long long we2 = ld2(wp + h * 288);       // uniform -> bcast
            unsigned long long wo2 = ld2(wp + h * 288 + 16);
            FMA2(acc2[h], va2, we2);
            FMA2(acc2[h], vb2, wo2);
        }
    }
    // unpack + store channel-section partials into tile[csec]
    {
        float* part = &sm->tile[csec][0];
#pragma unroll
        for (int h = 0; h < 16; ++h) {
            float lo = __uint_as_float((unsigned)acc2[h]);
            float hi = __uint_as_float((unsigned)(acc2[h] >> 32));
            part[posb * 16 + h] = lo + hi;
        }
    }
    __syncthreads();

    // final combine: thread -> (pos, h-quad)
    const int pos = tid >> 2, hq = tid & 3;
    const int alf = pos >> 4, bef = pos & 15;
    float vals[4];
#pragma unroll
    for (int k2 = 0; k2 < 4; ++k2) {
        int h = hq * 4 + k2;
        int idx = pos * 16 + h;
        float v = sm->tile[0][idx] + sm->tile[1][idx] + sm->tile[2][idx] +
                  sm->tile[3][idx] + sm->bb[h] + sm->rowt[alf][h] +
                  sm->colt[bef][h];
        vals[k2] = fmaxf(v, 0.f);
    }
    if (MODE == 1) {
        float4* out = (float4*)(g_F1 + (size_t)i * NODE_TILE + pos * 16 + hq * 4);
        *out = make_float4(vals[0], vals[1], vals[2], vals[3]);
    }
    // g reduction: sum over positions (lane bits 2..4 hold pos&7)
#pragma unroll
    for (int k2 = 0; k2 < 4; ++k2) {
        float v = vals[k2];
        v += __shfl_xor_sync(0xffffffffu, v, 4);
        v += __shfl_xor_sync(0xffffffffu, v, 8);
        v += __shfl_xor_sync(0xffffffffu, v, 16);
        vals[k2] = v;
    }
    if (lane < 4) {
#pragma unroll
        for (int k2 = 0; k2 < 4; ++k2) sm->red[w][lane * 4 + k2] = vals[k2];
    }
    __syncthreads();
    if (tid < 16) {
        float s = 0.f;
#pragma unroll
        for (int w2 = 0; w2 < 32; ++w2) s += sm->red[w2][tid];
        atomicAdd(&g_gsum[(MODE == 1 ? 16 : 32) + tid], (double)s);
    }
}

// ---------------- kernel 5: final dot with fc --------------------------------
__global__ void final_kernel(const float* __restrict__ fc_w,
                             const float* __restrict__ fc_b,
                             float* __restrict__ out) {
    if (threadIdx.x == 0) {
        double s = (double)fc_b[0];
#pragma unroll
        for (int c = 0; c < 48; ++c) s += g_gsum[c] * (double)fc_w[c];
        out[0] = (float)s;
    }
}

// ---------------- host entry --------------------------------------------------
extern "C" void kernel_launch(void* const* d_in, const int* in_sizes, int n_in,
                              void* d_out, int out_size) {
    const float* X   = (const float*)d_in[0];
    const float* adj = (const float*)d_in[1];
    const float* W1  = (const float*)d_in[2];
    const float* b1  = (const float*)d_in[3];
    const float* W2  = (const float*)d_in[4];
    const float* b2  = (const float*)d_in[5];
    const float* fcw = (const float*)d_in[6];
    const float* fcb = (const float*)d_in[7];
    float* out = (float*)d_out;

    const int SMEM = (int)sizeof(Sm);
    cudaFuncSetAttribute(step_kernel<1>,
                         cudaFuncAttributeMaxDynamicSharedMemorySize, SMEM);
    cudaFuncSetAttribute(step_kernel<2>,
                         cudaFuncAttributeMaxDynamicSharedMemorySize, SMEM);

    nbrs_kernel<<<250, 256>>>(adj);
    f0sum_kernel<<<125, 256>>>(X);
    step_kernel<1><<<NN, 1024, SMEM>>>(X, W1, b1);
    step_kernel<2><<<NN, 1024, SMEM>>>(X, W2, b2);
    final_kernel<<<1, 32>>>(fcw, fcb, out);
}